// round 7
// baseline (speedup 1.0000x reference)
#include <cuda_runtime.h>
#include <cuda_fp16.h>
#include <cstdint>
#include <math.h>

#define NS 8192
#define NE 8192
#define HH 512
#define PP 64
#define KC 128              // fp16 concat K = [hi(64) | lo(64)]

// fp16 split operands: [N, 128] row-major (256B per row).
__device__ __half g_sub_cat[(size_t)NS * KC];
__device__ __half g_edge_cat[(size_t)NE * KC];
// split-K partials: [which][khalf][row*64+col]
__device__ float g_part[2][2][(size_t)NS * PP];

__device__ __forceinline__ uint32_t smem_u32(const void* p) {
    uint32_t a;
    asm("{ .reg .u64 t; cvta.to.shared.u64 t, %1; cvt.u32.u64 %0, t; }" : "=r"(a) : "l"(p));
    return a;
}
__device__ __forceinline__ void ldmx4(uint32_t* r, uint32_t addr) {
    asm volatile("ldmatrix.sync.aligned.m8n8.x4.shared.b16 {%0,%1,%2,%3}, [%4];"
                 : "=r"(r[0]), "=r"(r[1]), "=r"(r[2]), "=r"(r[3]) : "r"(addr));
}
__device__ __forceinline__ void mma_f32(float* d, const uint32_t* a, const uint32_t* b) {
    asm volatile(
        "mma.sync.aligned.m16n8k16.row.col.f32.f16.f16.f32 "
        "{%0,%1,%2,%3}, {%4,%5,%6,%7}, {%8,%9}, {%0,%1,%2,%3};"
        : "+f"(d[0]), "+f"(d[1]), "+f"(d[2]), "+f"(d[3])
        : "r"(a[0]), "r"(a[1]), "r"(a[2]), "r"(a[3]), "r"(b[0]), "r"(b[1]));
}
__device__ __forceinline__ void mma_f16(uint32_t* d, const uint32_t* a, const uint32_t* b) {
    asm volatile(
        "mma.sync.aligned.m16n8k16.row.col.f16.f16.f16.f16 "
        "{%0,%1}, {%2,%3,%4,%5}, {%6,%7}, {%0,%1};"
        : "+r"(d[0]), "+r"(d[1])
        : "r"(a[0]), "r"(a[1]), "r"(a[2]), "r"(a[3]), "r"(b[0]), "r"(b[1]));
}
__device__ __forceinline__ void cpa16(uint32_t s, const void* g) {
    asm volatile("cp.async.cg.shared.global [%0], [%1], 16;" :: "r"(s), "l"(g) : "memory");
}

// ---------------------------------------------------------------------------
// proj stage 1: split-K GEMM partials.
// grid (128, 2, 2): x = 64-row block, y = k-half (256), z = which matrix.
// 64x64 tile, 4x4 microtile, 4 k-chunks of 64, register-staged double buffer.
// ---------------------------------------------------------------------------
__global__ __launch_bounds__(256) void proj_gemm(const float* __restrict__ Xs_in,
                                                 const float* __restrict__ Xe_in,
                                                 const float* __restrict__ Ws_in,
                                                 const float* __restrict__ We_in)
{
    __shared__ float Xs[64 * 64];   // [k][row]
    __shared__ float Ws[64 * 64];   // [k][col]

    const int which = blockIdx.z;
    const int kh    = blockIdx.y;
    const float4* X4 = reinterpret_cast<const float4*>(which ? Xe_in : Xs_in);
    const float4* W4 = reinterpret_cast<const float4*>(which ? We_in : Ws_in);

    const int tid = threadIdx.x;
    const int tx = tid & 15;
    const int ty = tid >> 4;
    const int rbase = blockIdx.x * 64;
    const int kbase = kh * 64;      // in float4 units (256 floats)

    float acc[4][4];
#pragma unroll
    for (int i = 0; i < 4; i++)
#pragma unroll
        for (int j = 0; j < 4; j++) acc[i][j] = 0.f;

    const int lrow = tid >> 4;      // 0..15? no: idx>>4 below
    (void)lrow;

    float4 xr[4], wr[4];
    // prologue: load chunk 0
#pragma unroll
    for (int it = 0; it < 4; it++) {
        int idx = tid + it * 256;
        int r = idx >> 4, q = idx & 15;
        xr[it] = X4[(size_t)(rbase + r) * 128 + kbase + q];
        wr[it] = W4[(size_t)r * 128 + kbase + q];
    }

#pragma unroll
    for (int c = 0; c < 4; c++) {
        // store staged chunk to smem (transposed)
#pragma unroll
        for (int it = 0; it < 4; it++) {
            int idx = tid + it * 256;
            int r = idx >> 4, q = idx & 15;
            Xs[(4 * q + 0) * 64 + r] = xr[it].x; Xs[(4 * q + 1) * 64 + r] = xr[it].y;
            Xs[(4 * q + 2) * 64 + r] = xr[it].z; Xs[(4 * q + 3) * 64 + r] = xr[it].w;
            Ws[(4 * q + 0) * 64 + r] = wr[it].x; Ws[(4 * q + 1) * 64 + r] = wr[it].y;
            Ws[(4 * q + 2) * 64 + r] = wr[it].z; Ws[(4 * q + 3) * 64 + r] = wr[it].w;
        }
        __syncthreads();

        // prefetch next chunk into registers (overlaps with compute below)
        if (c < 3) {
#pragma unroll
            for (int it = 0; it < 4; it++) {
                int idx = tid + it * 256;
                int r = idx >> 4, q = idx & 15;
                xr[it] = X4[(size_t)(rbase + r) * 128 + kbase + (c + 1) * 16 + q];
                wr[it] = W4[(size_t)r * 128 + kbase + (c + 1) * 16 + q];
            }
        }

#pragma unroll
        for (int k = 0; k < 64; k++) {
            float4 a  = *reinterpret_cast<const float4*>(&Xs[k * 64 + ty * 4]);
            float4 bv = *reinterpret_cast<const float4*>(&Ws[k * 64 + tx * 4]);
            const float av[4] = {a.x, a.y, a.z, a.w};
            const float bw[4] = {bv.x, bv.y, bv.z, bv.w};
#pragma unroll
            for (int i = 0; i < 4; i++)
#pragma unroll
                for (int j = 0; j < 4; j++)
                    acc[i][j] = fmaf(av[i], bw[j], acc[i][j]);
        }
        __syncthreads();
    }

    float* dst = g_part[which][kh];
#pragma unroll
    for (int i = 0; i < 4; i++) {
        *reinterpret_cast<float4*>(&dst[(size_t)(rbase + ty * 4 + i) * 64 + tx * 4]) =
            make_float4(acc[i][0], acc[i][1], acc[i][2], acc[i][3]);
    }
}

// ---------------------------------------------------------------------------
// proj stage 2: reduce k-halves + bias + L2-normalize + fp16 hi/lo split.
// warp per row; lane holds cols {2l, 2l+1}.
// ---------------------------------------------------------------------------
__global__ __launch_bounds__(256) void proj_norm(const float* __restrict__ bs,
                                                 const float* __restrict__ be)
{
    const int which = blockIdx.y;
    const int row  = blockIdx.x * 8 + (threadIdx.x >> 5);
    const int lane = threadIdx.x & 31;

    const float2* p0 = reinterpret_cast<const float2*>(&g_part[which][0][(size_t)row * 64]);
    const float2* p1 = reinterpret_cast<const float2*>(&g_part[which][1][(size_t)row * 64]);
    const float2* bb = reinterpret_cast<const float2*>(which ? be : bs);
    __half* out = which ? g_edge_cat : g_sub_cat;

    float2 a = p0[lane], b2 = p1[lane], bv = bb[lane];
    float v0 = a.x + b2.x + bv.x;
    float v1 = a.y + b2.y + bv.y;

    float ss = v0 * v0 + v1 * v1;
#pragma unroll
    for (int off = 16; off > 0; off >>= 1)
        ss += __shfl_xor_sync(0xffffffffu, ss, off);
    float inv = 1.0f / fmaxf(sqrtf(ss), 1e-12f);
    v0 *= inv; v1 *= inv;

    __half h0 = __float2half(v0), h1 = __float2half(v1);
    __half l0 = __float2half(v0 - __half2float(h0));
    __half l1 = __float2half(v1 - __half2float(h1));
    uint32_t hp = ((uint32_t)__half_as_ushort(h1) << 16) | __half_as_ushort(h0);
    uint32_t lp = ((uint32_t)__half_as_ushort(l1) << 16) | __half_as_ushort(l0);

    reinterpret_cast<uint32_t*>(&out[(size_t)row * KC])[lane]      = hp;
    reinterpret_cast<uint32_t*>(&out[(size_t)row * KC + 64])[lane] = lp;
}

// ---------------------------------------------------------------------------
// scores GEMM: 128x64 tile/CTA. K=128 fp16 [hi|lo] loaded once (48KB smem).
// hi*hi -> f32 accum;  hi*lo + lo*hi -> f16 accum (magnitude ~2^-12).
// ---------------------------------------------------------------------------
__global__ __launch_bounds__(256, 2) void scores_mma_kernel(const float* __restrict__ log_scale,
                                                            float* __restrict__ out)
{
    __shared__ char smem[49152];
    const uint32_t sA = smem_u32(smem);     // 32KB: 256 swizzle-rows of 128B
    const uint32_t sB = sA + 32768;         // 16KB: 128 swizzle-rows

    const int tid  = threadIdx.x;
    const int wid  = tid >> 5;
    const int lane = tid & 31;
    const int wm = wid & 3;        // 4 warps along M (32 each)
    const int wn = wid >> 2;       // 2 warps along N (32 each)
    const int brow = blockIdx.y * 128;
    const int bcol = blockIdx.x * 64;

    const char* gA = reinterpret_cast<const char*>(g_sub_cat);
    const char* gB = reinterpret_cast<const char*>(g_edge_cat);

#pragma unroll
    for (int it = 0; it < 8; it++) {
        int qi = tid + it * 256;
        int sr = qi >> 3, lq = qi & 7;
        int r = sr & 127, c = sr >> 7;
        cpa16(sA + sr * 128 + ((lq ^ (sr & 7)) << 4),
              gA + (size_t)(brow + r) * 256 + c * 128 + lq * 16);
    }
#pragma unroll
    for (int it = 0; it < 4; it++) {
        int qi = tid + it * 256;
        int sr = qi >> 3, lq = qi & 7;
        int r = sr & 63, c = sr >> 6;
        cpa16(sB + sr * 128 + ((lq ^ (sr & 7)) << 4),
              gB + (size_t)(bcol + r) * 256 + c * 128 + lq * 16);
    }
    asm volatile("cp.async.commit_group;" ::: "memory");
    asm volatile("cp.async.wait_group 0;" ::: "memory");
    __syncthreads();

    float    accf[2][4][4];
    uint32_t acch[2][4][2];
#pragma unroll
    for (int mt = 0; mt < 2; mt++)
#pragma unroll
        for (int nt = 0; nt < 4; nt++) {
#pragma unroll
            for (int q = 0; q < 4; q++) accf[mt][nt][q] = 0.f;
            acch[mt][nt][0] = 0u; acch[mt][nt][1] = 0u;
        }

    const int g  = lane >> 3;
    const int rl = lane & 7;
    const int gl = g & 1;
    const int gh = g >> 1;

    uint32_t aOff[2][2];   // [chunk][mt]
#pragma unroll
    for (int ca = 0; ca < 2; ca++)
#pragma unroll
        for (int mt = 0; mt < 2; mt++)
            aOff[ca][mt] = sA + (uint32_t)(ca * 128 + wm * 32 + mt * 16 + rl + gl * 8) * 128u;
    uint32_t bOff[2][2];   // [chunk][pn]
#pragma unroll
    for (int cb = 0; cb < 2; cb++)
#pragma unroll
        for (int pn = 0; pn < 2; pn++)
            bOff[cb][pn] = sB + (uint32_t)(cb * 64 + wn * 32 + pn * 16 + rl + gh * 8) * 128u;

#pragma unroll
    for (int s = 0; s < 4; s++) {
        const uint32_t ca_col = (uint32_t)(((2 * s + gh) ^ rl) << 4);
        const uint32_t cb_col = (uint32_t)(((2 * s + gl) ^ rl) << 4);
        uint32_t a0[2][4], a1[2][4], b0[2][4], b1[2][4];
#pragma unroll
        for (int mt = 0; mt < 2; mt++) {
            ldmx4(a0[mt], aOff[0][mt] + ca_col);   // hi
            ldmx4(a1[mt], aOff[1][mt] + ca_col);   // lo
        }
#pragma unroll
        for (int pn = 0; pn < 2; pn++) {
            ldmx4(b0[pn], bOff[0][pn] + cb_col);   // hi
            ldmx4(b1[pn], bOff[1][pn] + cb_col);   // lo
        }
#pragma unroll
        for (int mt = 0; mt < 2; mt++)
#pragma unroll
            for (int pn = 0; pn < 2; pn++) {
                mma_f32(accf[mt][2 * pn],     a0[mt], &b0[pn][0]);
                mma_f32(accf[mt][2 * pn + 1], a0[mt], &b0[pn][2]);
                mma_f16(acch[mt][2 * pn],     a0[mt], &b1[pn][0]);
                mma_f16(acch[mt][2 * pn + 1], a0[mt], &b1[pn][2]);
                mma_f16(acch[mt][2 * pn],     a1[mt], &b0[pn][0]);
                mma_f16(acch[mt][2 * pn + 1], a1[mt], &b0[pn][2]);
            }
    }

    const float zs = 0.5f * fminf(fmaxf(expf(*log_scale), 0.5f), 20.0f);

    const int r0 = brow + wm * 32 + (lane >> 2);
    const int c0 = bcol + wn * 32 + 2 * (lane & 3);
#pragma unroll
    for (int mt = 0; mt < 2; mt++)
#pragma unroll
        for (int nt = 0; nt < 4; nt++) {
            float2 c01 = __half22float2(*reinterpret_cast<__half2*>(&acch[mt][nt][0]));
            float2 c23 = __half22float2(*reinterpret_cast<__half2*>(&acch[mt][nt][1]));
            float* p0 = out + (size_t)(r0 + mt * 16) * NE + c0 + nt * 8;
            float* p1 = p0 + 8 * NE;
            *reinterpret_cast<float2*>(p0) =
                make_float2((accf[mt][nt][0] + c01.x) * zs, (accf[mt][nt][1] + c01.y) * zs);
            *reinterpret_cast<float2*>(p1) =
                make_float2((accf[mt][nt][2] + c23.x) * zs, (accf[mt][nt][3] + c23.y) * zs);
        }
}

// ---------------------------------------------------------------------------
// entmax-1.5 per row, in place. Newton on g(tau)=sqrt(sum relu(z-tau)^2)=1
// from tau0 = zmax-1 (monotone increasing). Candidates (z > zmax-1) are
// compacted to a smem pool once; Newton iterates over the pool.
// ---------------------------------------------------------------------------
__global__ __launch_bounds__(256) void entmax_kernel(float* __restrict__ out)
{
    __shared__ float pool[8192];
    __shared__ float red1[2][8], red2[2][8], smax[8];
    __shared__ int s_cnt;

    const int tid  = threadIdx.x;
    const int lane = tid & 31;
    const int warp = tid >> 5;
    float4* row = reinterpret_cast<float4*>(out + (size_t)blockIdx.x * NE);

    float4 v[8];
#pragma unroll
    for (int j = 0; j < 8; j++) v[j] = row[tid + 256 * j];

    if (tid == 0) s_cnt = 0;

    float m = -3.4e38f;
#pragma unroll
    for (int j = 0; j < 8; j++)
        m = fmaxf(m, fmaxf(fmaxf(v[j].x, v[j].y), fmaxf(v[j].z, v[j].w)));
#pragma unroll
    for (int off = 16; off > 0; off >>= 1)
        m = fmaxf(m, __shfl_xor_sync(0xffffffffu, m, off));
    if (lane == 0) smax[warp] = m;
    __syncthreads();
    float mm = smax[0];
#pragma unroll
    for (int w = 1; w < 8; w++) mm = fmaxf(mm, smax[w]);
    const float thr = mm - 1.0f;

    int nc = 0;
#pragma unroll
    for (int j = 0; j < 8; j++) {
        nc += (v[j].x > thr) + (v[j].y > thr) + (v[j].z > thr) + (v[j].w > thr);
    }
    int pref = nc;
#pragma unroll
    for (int off = 1; off < 32; off <<= 1) {
        int t = __shfl_up_sync(0xffffffffu, pref, off);
        if (lane >= off) pref += t;
    }
    int wtot = __shfl_sync(0xffffffffu, pref, 31);
    int wbase = 0;
    if (lane == 31) wbase = atomicAdd(&s_cnt, wtot);
    wbase = __shfl_sync(0xffffffffu, wbase, 31);
    int idx = wbase + pref - nc;
#pragma unroll
    for (int j = 0; j < 8; j++) {
        if (v[j].x > thr) pool[idx++] = v[j].x;
        if (v[j].y > thr) pool[idx++] = v[j].y;
        if (v[j].z > thr) pool[idx++] = v[j].z;
        if (v[j].w > thr) pool[idx++] = v[j].w;
    }
    __syncthreads();
    const int n = s_cnt;

    float tau = thr;
#pragma unroll 1
    for (int it = 0; it < 40; it++) {
        const int p = it & 1;
        float a = 0.f, q = 0.f;
        for (int i = tid; i < n; i += 256) {
            float d = fmaxf(pool[i] - tau, 0.f);
            a += d; q = fmaf(d, d, q);
        }
#pragma unroll
        for (int off = 16; off > 0; off >>= 1) {
            a += __shfl_xor_sync(0xffffffffu, a, off);
            q += __shfl_xor_sync(0xffffffffu, q, off);
        }
        if (lane == 0) { red1[p][warp] = a; red2[p][warp] = q; }
        __syncthreads();
        float S1 = 0.f, S2 = 0.f;
#pragma unroll
        for (int w = 0; w < 8; w++) { S1 += red1[p][w]; S2 += red2[p][w]; }
        if (S1 <= 0.f) break;
        float dt = (S2 - sqrtf(S2)) / S1;    // Newton step on g(tau)-1
        tau += dt;
        if (fabsf(dt) < 1e-7f) break;
    }

#pragma unroll
    for (int j = 0; j < 8; j++) {
        float4 o;
        float d;
        d = fmaxf(v[j].x - tau, 0.f); o.x = d * d;
        d = fmaxf(v[j].y - tau, 0.f); o.y = d * d;
        d = fmaxf(v[j].z - tau, 0.f); o.z = d * d;
        d = fmaxf(v[j].w - tau, 0.f); o.w = d * d;
        row[tid + 256 * j] = o;
    }
}

// ---------------------------------------------------------------------------
extern "C" void kernel_launch(void* const* d_in, const int* in_sizes, int n_in,
                              void* d_out, int out_size)
{
    const float* edge_repr = (const float*)d_in[0];
    const float* sub_repr  = (const float*)d_in[1];
    const float* W_sub     = (const float*)d_in[2];
    const float* b_sub     = (const float*)d_in[3];
    const float* W_edge    = (const float*)d_in[4];
    const float* b_edge    = (const float*)d_in[5];
    const float* log_scale = (const float*)d_in[6];
    float* out = (float*)d_out;

    proj_gemm<<<dim3(NS / 64, 2, 2), 256>>>(sub_repr, edge_repr, W_sub, W_edge);
    proj_norm<<<dim3(NS / 8, 2), 256>>>(b_sub, b_edge);

    dim3 grid(NE / 64, NS / 128);
    scores_mma_kernel<<<grid, 256>>>(log_scale, out);

    entmax_kernel<<<NS, 256>>>(out);
}